// round 2
// baseline (speedup 1.0000x reference)
#include <cuda_runtime.h>
#include <math.h>

// Scratch for per-batch modulated weights, layout [b][cin*9 + k][cout]
__device__ float g_wmod[8 * 288 * 32];

// ---------------------------------------------------------------------------
// f32x2 packed helpers
// ---------------------------------------------------------------------------
__device__ __forceinline__ unsigned long long pack2(float lo, float hi) {
    unsigned long long r;
    asm("mov.b64 %0, {%1, %2};" : "=l"(r) : "f"(lo), "f"(hi));
    return r;
}
__device__ __forceinline__ void unpack2(unsigned long long v, float& lo, float& hi) {
    asm("mov.b64 {%0, %1}, %2;" : "=f"(lo), "=f"(hi) : "l"(v));
}
__device__ __forceinline__ void fma2(unsigned long long& d,
                                     unsigned long long a,
                                     unsigned long long b) {
    asm("fma.rn.f32x2 %0, %1, %2, %0;" : "+l"(d) : "l"(a), "l"(b));
}

// ---------------------------------------------------------------------------
// Kernel 1: compute modulated + demodulated weights.
// grid = 8, block = 256
// ---------------------------------------------------------------------------
__global__ void modw_kernel(const float* __restrict__ style,
                            const float* __restrict__ weight,
                            const float* __restrict__ mod_w,
                            const float* __restrict__ mod_b)
{
    const int b    = blockIdx.x;
    const int tid  = threadIdx.x;
    const int warp = tid >> 5;
    const int lane = tid & 31;

    __shared__ float s_s[32];

    const float mod_scale  = 1.0f / sqrtf(512.0f);
    const float conv_scale = 1.0f / sqrtf(288.0f);

    #pragma unroll
    for (int i = 0; i < 4; i++) {
        int cin = warp + 8 * i;
        float acc = 0.f;
        const float* st = style + b * 512;
        const float* mw = mod_w + cin * 512;
        for (int j = lane; j < 512; j += 32)
            acc += st[j] * mw[j];
        #pragma unroll
        for (int off = 16; off; off >>= 1)
            acc += __shfl_xor_sync(0xffffffffu, acc, off);
        if (lane == 0)
            s_s[cin] = acc * mod_scale + mod_b[cin];
    }
    __syncthreads();

    #pragma unroll
    for (int i = 0; i < 4; i++) {
        int cout = warp + 8 * i;
        float vals[9];
        float ss = 0.f;
        #pragma unroll
        for (int j = 0; j < 9; j++) {
            int f   = lane + 32 * j;
            int cin = f / 9;
            int k   = f % 9;
            float v = conv_scale * weight[(cout * 32 + cin) * 9 + k] * s_s[cin];
            vals[j] = v;
            ss += v * v;
        }
        #pragma unroll
        for (int off = 16; off; off >>= 1)
            ss += __shfl_xor_sync(0xffffffffu, ss, off);
        float demod = rsqrtf(ss + 1e-8f);
        #pragma unroll
        for (int j = 0; j < 9; j++) {
            int f = lane + 32 * j;
            g_wmod[(b * 288 + f) * 32 + cout] = vals[j] * demod;
        }
    }
}

// ---------------------------------------------------------------------------
// Kernel 2: direct conv with packed f32x2 FMA.
// Tile 64x8 pixels, 512 threads: 4 cout-groups of 8 couts;
// each thread owns 4 consecutive x-pixels (2 packed pairs) of one row.
// ---------------------------------------------------------------------------
#define TW 64
#define TH 8
#define XS_W 68
#define XS_H 10

__global__ __launch_bounds__(512, 1)
void conv_kernel(const float* __restrict__ x, float* __restrict__ out)
{
    extern __shared__ float smem[];
    float*  sx  = smem;                                  // [32][10][68]
    float2* sw2 = (float2*)(smem + 32 * XS_H * XS_W);    // [288][32] dup pairs

    const int b   = blockIdx.z;
    const int tx0 = blockIdx.x * TW;
    const int ty0 = blockIdx.y * TH;
    const int tid = threadIdx.x;

    // ---- stage weights, duplicated into (w,w) pairs ----
    {
        const float* wsrc = g_wmod + b * 288 * 32;
        for (int i = tid; i < 288 * 32; i += 512) {
            float v = wsrc[i];
            sw2[i] = make_float2(v, v);
        }
    }

    // ---- stage input halo tile: 32 cin x 10 x 66 (zero-padded) ----
    {
        const float* xb = x + (size_t)b * 32 * 512 * 512;
        for (int i = tid; i < 32 * XS_H * 66; i += 512) {
            int cin = i / (XS_H * 66);
            int r   = i % (XS_H * 66);
            int ly  = r / 66;
            int lx  = r % 66;
            int gy  = ty0 - 1 + ly;
            int gx  = tx0 - 1 + lx;
            float v = 0.f;
            if ((unsigned)gy < 512u && (unsigned)gx < 512u)
                v = xb[(size_t)cin * 512 * 512 + gy * 512 + gx];
            sx[(cin * XS_H + ly) * XS_W + lx] = v;
        }
    }
    __syncthreads();

    const int cog = tid >> 7;          // cout group 0..3 (8 couts each)
    const int t   = tid & 127;
    const int y   = t >> 4;            // 0..7
    const int x0  = (t & 15) << 2;     // 0..60

    unsigned long long acc[8][2];
    #pragma unroll
    for (int c = 0; c < 8; c++) { acc[c][0] = 0ull; acc[c][1] = 0ull; }

    #pragma unroll 1
    for (int cin = 0; cin < 32; cin++) {
        const float* sxc = sx + (cin * XS_H + y) * XS_W + x0;
        #pragma unroll
        for (int ky = 0; ky < 3; ky++) {
            const float* row = sxc + ky * XS_W;
            float4 r03 = *(const float4*)row;
            float2 r45 = *(const float2*)(row + 4);
            unsigned long long xp[3][2];
            xp[0][0] = pack2(r03.x, r03.y);  xp[0][1] = pack2(r03.z, r03.w);
            xp[1][0] = pack2(r03.y, r03.z);  xp[1][1] = pack2(r03.w, r45.x);
            xp[2][0] = xp[0][1];             xp[2][1] = pack2(r45.x, r45.y);
            #pragma unroll
            for (int kx = 0; kx < 3; kx++) {
                const float2* wp = sw2 + (cin * 9 + ky * 3 + kx) * 32 + cog * 8;
                ulonglong2 wA = *(const ulonglong2*)(wp + 0);
                ulonglong2 wB = *(const ulonglong2*)(wp + 2);
                ulonglong2 wC = *(const ulonglong2*)(wp + 4);
                ulonglong2 wD = *(const ulonglong2*)(wp + 6);
                unsigned long long wv[8] = {wA.x, wA.y, wB.x, wB.y,
                                            wC.x, wC.y, wD.x, wD.y};
                #pragma unroll
                for (int c = 0; c < 8; c++) {
                    fma2(acc[c][0], xp[kx][0], wv[c]);
                    fma2(acc[c][1], xp[kx][1], wv[c]);
                }
            }
        }
    }

    // ---- epilogue: coalesced float4 stores ----
    const int gy = ty0 + y;
    #pragma unroll
    for (int c = 0; c < 8; c++) {
        float4 v;
        unpack2(acc[c][0], v.x, v.y);
        unpack2(acc[c][1], v.z, v.w);
        size_t off = (((size_t)b * 32 + cog * 8 + c) * 512 + gy) * 512 + tx0 + x0;
        *(float4*)(out + off) = v;
    }
}

// ---------------------------------------------------------------------------
extern "C" void kernel_launch(void* const* d_in, const int* in_sizes, int n_in,
                              void* d_out, int out_size)
{
    const float* x      = (const float*)d_in[0];
    const float* style  = (const float*)d_in[1];
    const float* weight = (const float*)d_in[2];
    const float* mod_w  = (const float*)d_in[3];
    const float* mod_b  = (const float*)d_in[4];
    float* out = (float*)d_out;

    const int smem_bytes = (32 * XS_H * XS_W) * 4 + 288 * 32 * 8; // 160,768
    cudaFuncSetAttribute(conv_kernel,
                         cudaFuncAttributeMaxDynamicSharedMemorySize, smem_bytes);

    modw_kernel<<<8, 256>>>(style, weight, mod_w, mod_b);

    dim3 grid(512 / TW, 512 / TH, 8);
    conv_kernel<<<grid, 512, smem_bytes>>>(x, out);
}

// round 3
// speedup vs baseline: 1.0006x; 1.0006x over previous
#include <cuda_runtime.h>
#include <math.h>

// Scratch for per-batch modulated weights, layout [b][cin*9 + k][cout]
__device__ float g_wmod[8 * 288 * 32];

// ---------------------------------------------------------------------------
// f32x2 packed helpers
// ---------------------------------------------------------------------------
__device__ __forceinline__ unsigned long long pack2(float lo, float hi) {
    unsigned long long r;
    asm("mov.b64 %0, {%1, %2};" : "=l"(r) : "f"(lo), "f"(hi));
    return r;
}
__device__ __forceinline__ void unpack2(unsigned long long v, float& lo, float& hi) {
    asm("mov.b64 {%0, %1}, %2;" : "=f"(lo), "=f"(hi) : "l"(v));
}
__device__ __forceinline__ void fma2(unsigned long long& d,
                                     unsigned long long a,
                                     unsigned long long b) {
    asm("fma.rn.f32x2 %0, %1, %2, %0;" : "+l"(d) : "l"(a), "l"(b));
}

// ---------------------------------------------------------------------------
// Kernel 1: compute modulated + demodulated weights.
// grid = 8, block = 256
// ---------------------------------------------------------------------------
__global__ void modw_kernel(const float* __restrict__ style,
                            const float* __restrict__ weight,
                            const float* __restrict__ mod_w,
                            const float* __restrict__ mod_b)
{
    const int b    = blockIdx.x;
    const int tid  = threadIdx.x;
    const int warp = tid >> 5;
    const int lane = tid & 31;

    __shared__ float s_s[32];

    const float mod_scale  = 1.0f / sqrtf(512.0f);
    const float conv_scale = 1.0f / sqrtf(288.0f);

    #pragma unroll
    for (int i = 0; i < 4; i++) {
        int cin = warp + 8 * i;
        float acc = 0.f;
        const float* st = style + b * 512;
        const float* mw = mod_w + cin * 512;
        for (int j = lane; j < 512; j += 32)
            acc += st[j] * mw[j];
        #pragma unroll
        for (int off = 16; off; off >>= 1)
            acc += __shfl_xor_sync(0xffffffffu, acc, off);
        if (lane == 0)
            s_s[cin] = acc * mod_scale + mod_b[cin];
    }
    __syncthreads();

    #pragma unroll
    for (int i = 0; i < 4; i++) {
        int cout = warp + 8 * i;
        float vals[9];
        float ss = 0.f;
        #pragma unroll
        for (int j = 0; j < 9; j++) {
            int f   = lane + 32 * j;
            int cin = f / 9;
            int k   = f % 9;
            float v = conv_scale * weight[(cout * 32 + cin) * 9 + k] * s_s[cin];
            vals[j] = v;
            ss += v * v;
        }
        #pragma unroll
        for (int off = 16; off; off >>= 1)
            ss += __shfl_xor_sync(0xffffffffu, ss, off);
        float demod = rsqrtf(ss + 1e-8f);
        #pragma unroll
        for (int j = 0; j < 9; j++) {
            int f = lane + 32 * j;
            g_wmod[(b * 288 + f) * 32 + cout] = vals[j] * demod;
        }
    }
}

// ---------------------------------------------------------------------------
// Kernel 2: direct conv with packed f32x2 FMA.
// Tile 64x8 pixels, 512 threads: 4 cout-groups of 8 couts;
// each thread owns 4 consecutive x-pixels (2 packed pairs) of one row.
// ---------------------------------------------------------------------------
#define TW 64
#define TH 8
#define XS_W 68
#define XS_H 10

__global__ __launch_bounds__(512, 1)
void conv_kernel(const float* __restrict__ x, float* __restrict__ out)
{
    extern __shared__ float smem[];
    float*  sx  = smem;                                  // [32][10][68]
    float2* sw2 = (float2*)(smem + 32 * XS_H * XS_W);    // [288][32] dup pairs

    const int b   = blockIdx.z;
    const int tx0 = blockIdx.x * TW;
    const int ty0 = blockIdx.y * TH;
    const int tid = threadIdx.x;

    // ---- stage weights, duplicated into (w,w) pairs ----
    {
        const float* wsrc = g_wmod + b * 288 * 32;
        for (int i = tid; i < 288 * 32; i += 512) {
            float v = wsrc[i];
            sw2[i] = make_float2(v, v);
        }
    }

    // ---- stage input halo tile: 32 cin x 10 x 66 (zero-padded) ----
    {
        const float* xb = x + (size_t)b * 32 * 512 * 512;
        for (int i = tid; i < 32 * XS_H * 66; i += 512) {
            int cin = i / (XS_H * 66);
            int r   = i % (XS_H * 66);
            int ly  = r / 66;
            int lx  = r % 66;
            int gy  = ty0 - 1 + ly;
            int gx  = tx0 - 1 + lx;
            float v = 0.f;
            if ((unsigned)gy < 512u && (unsigned)gx < 512u)
                v = xb[(size_t)cin * 512 * 512 + gy * 512 + gx];
            sx[(cin * XS_H + ly) * XS_W + lx] = v;
        }
    }
    __syncthreads();

    const int cog = tid >> 7;          // cout group 0..3 (8 couts each)
    const int t   = tid & 127;
    const int y   = t >> 4;            // 0..7
    const int x0  = (t & 15) << 2;     // 0..60

    unsigned long long acc[8][2];
    #pragma unroll
    for (int c = 0; c < 8; c++) { acc[c][0] = 0ull; acc[c][1] = 0ull; }

    #pragma unroll 1
    for (int cin = 0; cin < 32; cin++) {
        const float* sxc = sx + (cin * XS_H + y) * XS_W + x0;
        #pragma unroll
        for (int ky = 0; ky < 3; ky++) {
            const float* row = sxc + ky * XS_W;
            float4 r03 = *(const float4*)row;
            float2 r45 = *(const float2*)(row + 4);
            unsigned long long xp[3][2];
            xp[0][0] = pack2(r03.x, r03.y);  xp[0][1] = pack2(r03.z, r03.w);
            xp[1][0] = pack2(r03.y, r03.z);  xp[1][1] = pack2(r03.w, r45.x);
            xp[2][0] = xp[0][1];             xp[2][1] = pack2(r45.x, r45.y);
            #pragma unroll
            for (int kx = 0; kx < 3; kx++) {
                const float2* wp = sw2 + (cin * 9 + ky * 3 + kx) * 32 + cog * 8;
                ulonglong2 wA = *(const ulonglong2*)(wp + 0);
                ulonglong2 wB = *(const ulonglong2*)(wp + 2);
                ulonglong2 wC = *(const ulonglong2*)(wp + 4);
                ulonglong2 wD = *(const ulonglong2*)(wp + 6);
                unsigned long long wv[8] = {wA.x, wA.y, wB.x, wB.y,
                                            wC.x, wC.y, wD.x, wD.y};
                #pragma unroll
                for (int c = 0; c < 8; c++) {
                    fma2(acc[c][0], xp[kx][0], wv[c]);
                    fma2(acc[c][1], xp[kx][1], wv[c]);
                }
            }
        }
    }

    // ---- epilogue: coalesced float4 stores ----
    const int gy = ty0 + y;
    #pragma unroll
    for (int c = 0; c < 8; c++) {
        float4 v;
        unpack2(acc[c][0], v.x, v.y);
        unpack2(acc[c][1], v.z, v.w);
        size_t off = (((size_t)b * 32 + cog * 8 + c) * 512 + gy) * 512 + tx0 + x0;
        *(float4*)(out + off) = v;
    }
}

// ---------------------------------------------------------------------------
extern "C" void kernel_launch(void* const* d_in, const int* in_sizes, int n_in,
                              void* d_out, int out_size)
{
    const float* x      = (const float*)d_in[0];
    const float* style  = (const float*)d_in[1];
    const float* weight = (const float*)d_in[2];
    const float* mod_w  = (const float*)d_in[3];
    const float* mod_b  = (const float*)d_in[4];
    float* out = (float*)d_out;

    const int smem_bytes = (32 * XS_H * XS_W) * 4 + 288 * 32 * 8; // 160,768
    cudaFuncSetAttribute(conv_kernel,
                         cudaFuncAttributeMaxDynamicSharedMemorySize, smem_bytes);

    modw_kernel<<<8, 256>>>(style, weight, mod_w, mod_b);

    dim3 grid(512 / TW, 512 / TH, 8);
    conv_kernel<<<grid, 512, smem_bytes>>>(x, out);
}

// round 5
// speedup vs baseline: 2.5806x; 2.5790x over previous
#include <cuda_runtime.h>
#include <cuda_bf16.h>
#include <cstdint>
#include <math.h>

// Modulated weights as bf16 hi/lo planes: [b][var][cout=32][k=296(288+pad)]
__device__ unsigned short g_wB[8][2][32][296];

#define AYS   2720u      // A y-stride bytes: 34 x-slots * 80
#define APS   27200u     // A plane size: 10 * AYS
#define BLD   592u       // B row stride bytes (296 bf16)
#define BPS   18944u     // B plane (variant) size: 32 * 592
#define BOFF  54400u     // B offset in smem (after 2 A planes)
#define SMEM_BYTES (54400 + 37888)   // 92,288

__device__ __forceinline__ uint32_t smem_u32(const void* p) {
    uint32_t a;
    asm("{ .reg .u64 t; cvta.to.shared.u64 t, %1; cvt.u32.u64 %0, t; }"
        : "=r"(a) : "l"(p));
    return a;
}
__device__ __forceinline__ void ldsm4(uint32_t* r, uint32_t addr) {
    asm volatile("ldmatrix.sync.aligned.m8n8.x4.shared.b16 {%0,%1,%2,%3}, [%4];"
                 : "=r"(r[0]), "=r"(r[1]), "=r"(r[2]), "=r"(r[3]) : "r"(addr));
}
__device__ __forceinline__ void mma16816(float* d, const uint32_t* a,
                                         uint32_t b0, uint32_t b1) {
    asm volatile(
        "mma.sync.aligned.m16n8k16.row.col.f32.bf16.bf16.f32 "
        "{%0,%1,%2,%3},{%4,%5,%6,%7},{%8,%9},{%0,%1,%2,%3};"
        : "+f"(d[0]), "+f"(d[1]), "+f"(d[2]), "+f"(d[3])
        : "r"(a[0]), "r"(a[1]), "r"(a[2]), "r"(a[3]), "r"(b0), "r"(b1));
}

// ---------------------------------------------------------------------------
// Kernel 1: modulate + demodulate, emit bf16 hi/lo weight matrices.
// grid = 8, block = 256
// ---------------------------------------------------------------------------
__global__ void modw_kernel(const float* __restrict__ style,
                            const float* __restrict__ weight,
                            const float* __restrict__ mod_w,
                            const float* __restrict__ mod_b)
{
    const int b    = blockIdx.x;
    const int tid  = threadIdx.x;
    const int warp = tid >> 5;
    const int lane = tid & 31;

    __shared__ float s_s[32];
    __shared__ float s_d[32];

    const float mod_scale  = 1.0f / sqrtf(512.0f);
    const float conv_scale = 1.0f / sqrtf(288.0f);

    #pragma unroll
    for (int i = 0; i < 4; i++) {
        int cin = warp + 8 * i;
        float acc = 0.f;
        const float* st = style + b * 512;
        const float* mw = mod_w + cin * 512;
        for (int j = lane; j < 512; j += 32)
            acc += st[j] * mw[j];
        #pragma unroll
        for (int off = 16; off; off >>= 1)
            acc += __shfl_xor_sync(0xffffffffu, acc, off);
        if (lane == 0)
            s_s[cin] = acc * mod_scale + mod_b[cin];
    }
    __syncthreads();

    #pragma unroll
    for (int i = 0; i < 4; i++) {
        int cout = warp + 8 * i;
        float ss = 0.f;
        #pragma unroll
        for (int j = 0; j < 9; j++) {
            int f   = lane + 32 * j;
            int cin = f / 9;
            int t   = f % 9;
            float v = conv_scale * weight[(cout * 32 + cin) * 9 + t] * s_s[cin];
            ss += v * v;
        }
        #pragma unroll
        for (int off = 16; off; off >>= 1)
            ss += __shfl_xor_sync(0xffffffffu, ss, off);
        if (lane == 0)
            s_d[cout] = rsqrtf(ss + 1e-8f);
    }
    __syncthreads();

    // Emit: k index = tap*32 + cin  (chunks of 16 stay within one tap)
    for (int idx = tid; idx < 9216; idx += 256) {
        int t  = idx >> 10;
        int co = (idx >> 5) & 31;
        int ci = idx & 31;
        float w = conv_scale * weight[(co * 32 + ci) * 9 + t] * s_s[ci] * s_d[co];
        __nv_bfloat16 hi = __float2bfloat16(w);
        __nv_bfloat16 lo = __float2bfloat16(w - __bfloat162float(hi));
        g_wB[b][0][co][t * 32 + ci] = __bfloat16_as_ushort(hi);
        g_wB[b][1][co][t * 32 + ci] = __bfloat16_as_ushort(lo);
    }
}

// ---------------------------------------------------------------------------
// Kernel 2: tensor-core conv (mma.sync bf16, 3-pass hi/lo).
// Tile 32(W) x 8(H); 8 warps, warp = one row (2 m16-tiles).
// grid = (16, 64, 8); block = 256; 2 CTAs/SM.
// ---------------------------------------------------------------------------
__global__ __launch_bounds__(256, 2)
void conv_kernel(const float* __restrict__ x, float* __restrict__ out)
{
    extern __shared__ unsigned char smem[];
    const int tid  = threadIdx.x;
    const int lane = tid & 31;
    const int warp = tid >> 5;
    const int b    = blockIdx.z;
    const int x0   = blockIdx.x * 32;
    const int y0   = blockIdx.y * 8;

    // ---- stage B (both variants, 37,888 B) ----
    {
        const uint4* src = (const uint4*)&g_wB[b][0][0][0];
        uint4* dst = (uint4*)(smem + BOFF);
        for (int i = tid; i < 37888 / 16; i += 256)
            dst[i] = src[i];
    }

    // ---- stage A halo 10 x 34 x 32cin as bf16 hi/lo planes [y][x][cin] ----
    {
        const float* xb = x + (size_t)b * 32 * 262144;
        for (int e = tid; e < 10 * 32 * 34; e += 256) {
            int xi   = e % 34;
            int rest = e / 34;
            int cin  = rest & 31;
            int y    = rest >> 5;
            int gx = x0 - 1 + xi;
            int gy = y0 - 1 + y;
            float v = 0.f;
            if ((unsigned)gx < 512u && (unsigned)gy < 512u)
                v = xb[(size_t)cin * 262144 + (size_t)gy * 512 + gx];
            __nv_bfloat16 h = __float2bfloat16(v);
            __nv_bfloat16 l = __float2bfloat16(v - __bfloat162float(h));
            uint32_t off = (uint32_t)y * AYS + (uint32_t)xi * 80 + (uint32_t)cin * 2;
            *(unsigned short*)(smem + off)       = __bfloat16_as_ushort(h);
            *(unsigned short*)(smem + off + APS) = __bfloat16_as_ushort(l);
        }
    }
    __syncthreads();

    const uint32_t sb = smem_u32(smem);
    // ldmatrix lane addressing
    const uint32_t aLane = (uint32_t)(((lane & 7) + ((lane >> 3) & 1) * 8) * 80
                                      + (lane >> 4) * 16);
    const uint32_t bLane = (uint32_t)((lane & 7) * BLD + (lane >> 3) * 16);

    const int y = warp;
    float d[2][4][4];
    #pragma unroll
    for (int mt = 0; mt < 2; mt++)
        #pragma unroll
        for (int nt = 0; nt < 4; nt++)
            #pragma unroll
            for (int r = 0; r < 4; r++)
                d[mt][nt][r] = 0.f;

    #pragma unroll 1
    for (int tap = 0; tap < 9; tap++) {
        const int ky = tap / 3;
        const int kx = tap - 3 * ky;

        // B fragments for this tap: [var][nt][4 regs] (r0,r1=chunk0; r2,r3=chunk1)
        uint32_t Bf[2][4][4];
        const uint32_t bB = sb + BOFF + (uint32_t)tap * 64 + bLane;
        #pragma unroll
        for (int v = 0; v < 2; v++)
            #pragma unroll
            for (int nt = 0; nt < 4; nt++)
                ldsm4(Bf[v][nt], bB + (uint32_t)v * BPS + (uint32_t)nt * 8 * BLD);

        const uint32_t aB = sb + (uint32_t)(y + ky) * AYS + (uint32_t)kx * 80 + aLane;
        #pragma unroll
        for (int mt = 0; mt < 2; mt++) {
            uint32_t Ah0[4], Ah1[4], Al0[4], Al1[4];
            const uint32_t ab = aB + (uint32_t)mt * (16 * 80);
            ldsm4(Ah0, ab);
            ldsm4(Ah1, ab + 32);
            ldsm4(Al0, ab + APS);
            ldsm4(Al1, ab + APS + 32);
            #pragma unroll
            for (int nt = 0; nt < 4; nt++) {
                mma16816(d[mt][nt], Ah0, Bf[0][nt][0], Bf[0][nt][1]);
                mma16816(d[mt][nt], Ah1, Bf[0][nt][2], Bf[0][nt][3]);
                mma16816(d[mt][nt], Ah0, Bf[1][nt][0], Bf[1][nt][1]);
                mma16816(d[mt][nt], Ah1, Bf[1][nt][2], Bf[1][nt][3]);
                mma16816(d[mt][nt], Al0, Bf[0][nt][0], Bf[0][nt][1]);
                mma16816(d[mt][nt], Al1, Bf[0][nt][2], Bf[0][nt][3]);
            }
        }
    }

    // ---- store ----
    const int gy   = y0 + y;
    const int prow = lane >> 2;
    const int cob  = (lane & 3) * 2;
    #pragma unroll
    for (int mt = 0; mt < 2; mt++) {
        #pragma unroll
        for (int nt = 0; nt < 4; nt++) {
            int p  = x0 + mt * 16 + prow;
            int co = nt * 8 + cob;
            size_t o0 = (((size_t)(b * 32 + co) * 512) + gy) * 512 + p;
            out[o0]              = d[mt][nt][0];
            out[o0 + 262144]     = d[mt][nt][1];   // co+1
            out[o0 + 8]          = d[mt][nt][2];   // pixel row +8
            out[o0 + 262144 + 8] = d[mt][nt][3];
        }
    }
}

// ---------------------------------------------------------------------------
extern "C" void kernel_launch(void* const* d_in, const int* in_sizes, int n_in,
                              void* d_out, int out_size)
{
    const float* x      = (const float*)d_in[0];
    const float* style  = (const float*)d_in[1];
    const float* weight = (const float*)d_in[2];
    const float* mod_w  = (const float*)d_in[3];
    const float* mod_b  = (const float*)d_in[4];
    float* out = (float*)d_out;

    cudaFuncSetAttribute(conv_kernel,
                         cudaFuncAttributeMaxDynamicSharedMemorySize, SMEM_BYTES);

    modw_kernel<<<8, 256>>>(style, weight, mod_w, mod_b);

    dim3 grid(16, 64, 8);
    conv_kernel<<<grid, 256, SMEM_BYTES>>>(x, out);
}